// round 2
// baseline (speedup 1.0000x reference)
#include <cuda_runtime.h>

#define P 16384
#define H 256
#define E 64
#define NA 64
#define PE (P*E)

// ---------------- static scratch (no allocs allowed) ----------------
__device__ float g_tsum[H], g_tsumsq[H];     // temp BN sums
__device__ float g_ssum[H], g_ssumsq[H];     // spat BN sums
__device__ float g_te[P*NA];                 // temporal embed [P,64]   4MB
__device__ float g_c[P];                     // c[p] = b_spat . te[p]
__device__ float g_v[P*H];                   // v[p,h]                 16MB
__device__ float g_Vg[P*4];                  // group sums of v
__device__ float g_D[P*H];                   // raw dots               16MB
__device__ float g_ss[H], g_tt[H];           // spat BN scale/shift
__device__ float g_attnT[E*P];               // attn transposed         4MB
__device__ float g_wv[P*E];                  // softmax weights         4MB

// ---------------- init: zero the atomically-accumulated buffers ----------------
__global__ void k_init() {
    int i = blockIdx.x * blockDim.x + threadIdx.x;
    int stride = gridDim.x * blockDim.x;
    if (i < H) { g_tsum[i] = 0.f; g_tsumsq[i] = 0.f; g_ssum[i] = 0.f; g_ssumsq[i] = 0.f; }
    for (int j = i; j < P;   j += stride) g_c[j]  = 0.f;
    for (int j = i; j < P*4; j += stride) g_Vg[j] = 0.f;
}

// ---------------- temp_hidden per-column stats ----------------
__global__ void k_tstats(const float* __restrict__ th) {
    int c = threadIdx.x;                       // 256 threads = H columns
    float s = 0.f, s2 = 0.f;
    for (int p = blockIdx.x; p < P; p += gridDim.x) {
        float x = th[(size_t)p*H + c];
        s += x; s2 += x*x;
    }
    atomicAdd(&g_tsum[c], s);
    atomicAdd(&g_tsumsq[c], s2);
}

// ---------------- te = BN(temp) @ w_temp^T + b_temp ; c[p] = te . b_spat ----------------
// 64 persons per block, 256 threads, 4x4 register tile
__global__ void __launch_bounds__(256) k_te(const float* __restrict__ th,
                                            const float* __restrict__ gamma,
                                            const float* __restrict__ beta,
                                            const float* __restrict__ wt,
                                            const float* __restrict__ bt,
                                            const float* __restrict__ bs) {
    extern __shared__ float sm[];
    float* s_tn  = sm;                 // [64][260]
    float* s_wtT = sm + 64*260;        // [256][68]  (transposed w_temp)
    float* s_sc  = s_wtT + 256*68;     // [256]
    float* s_sh  = s_sc + 256;         // [256]
    int tid = threadIdx.x;
    int pbase = blockIdx.x * 64;

    {   // BN scale/shift per column
        float m   = g_tsum[tid]   * (1.0f/P);
        float var = g_tsumsq[tid] * (1.0f/P) - m*m;
        float s   = gamma[tid] * rsqrtf(var + 1e-5f);
        s_sc[tid] = s;
        s_sh[tid] = beta[tid] - m*s;
    }
    __syncthreads();

    int c4 = (tid & 63) * 4, r0 = tid >> 6;
    for (int r = r0; r < 64; r += 4) {                // stage normalized tn
        float4 x = *(const float4*)&th[(size_t)(pbase + r)*H + c4];
        x.x = x.x*s_sc[c4+0] + s_sh[c4+0];
        x.y = x.y*s_sc[c4+1] + s_sh[c4+1];
        x.z = x.z*s_sc[c4+2] + s_sh[c4+2];
        x.w = x.w*s_sc[c4+3] + s_sh[c4+3];
        *(float4*)&s_tn[r*260 + c4] = x;
    }
    for (int r = r0; r < 64; r += 4) {                // stage w_temp transposed
        float4 w = *(const float4*)&wt[(size_t)r*H + c4];
        s_wtT[(c4+0)*68 + r] = w.x;
        s_wtT[(c4+1)*68 + r] = w.y;
        s_wtT[(c4+2)*68 + r] = w.z;
        s_wtT[(c4+3)*68 + r] = w.w;
    }
    __syncthreads();

    int ty = tid >> 4, tx = tid & 15;   // 16x16 thread grid -> 64x64 outputs
    float acc[4][4] = {};
    #pragma unroll 4
    for (int k = 0; k < 256; k++) {
        float a0 = s_tn[(ty*4+0)*260 + k];
        float a1 = s_tn[(ty*4+1)*260 + k];
        float a2 = s_tn[(ty*4+2)*260 + k];
        float a3 = s_tn[(ty*4+3)*260 + k];
        float4 b = *(float4*)&s_wtT[k*68 + tx*4];
        acc[0][0] += a0*b.x; acc[0][1] += a0*b.y; acc[0][2] += a0*b.z; acc[0][3] += a0*b.w;
        acc[1][0] += a1*b.x; acc[1][1] += a1*b.y; acc[1][2] += a1*b.z; acc[1][3] += a1*b.w;
        acc[2][0] += a2*b.x; acc[2][1] += a2*b.y; acc[2][2] += a2*b.z; acc[2][3] += a2*b.w;
        acc[3][0] += a3*b.x; acc[3][1] += a3*b.y; acc[3][2] += a3*b.z; acc[3][3] += a3*b.w;
    }
    float4 bt4 = *(const float4*)&bt[tx*4];
    float4 bs4 = *(const float4*)&bs[tx*4];
    #pragma unroll
    for (int i = 0; i < 4; i++) {
        int p = pbase + ty*4 + i;
        float4 t;
        t.x = acc[i][0] + bt4.x;
        t.y = acc[i][1] + bt4.y;
        t.z = acc[i][2] + bt4.z;
        t.w = acc[i][3] + bt4.w;
        *(float4*)&g_te[(size_t)p*NA + tx*4] = t;
        float cc = t.x*bs4.x + t.y*bs4.y + t.z*bs4.z + t.w*bs4.w;
        atomicAdd(&g_c[p], cc);
    }
}

// ---------------- v = te @ w_spat ; Vg[p][g] = sum over 64-chunk of v ----------------
// 64 persons per block, 256 threads, 8x8 register tile
__global__ void __launch_bounds__(256) k_v(const float* __restrict__ ws) {
    extern __shared__ float sm[];
    float* s_te = sm;             // [64][68]
    float* s_ws = sm + 64*68;     // [64][260]
    int tid = threadIdx.x, pbase = blockIdx.x * 64;

    for (int i = tid; i < 64*64; i += 256)
        s_te[(i>>6)*68 + (i&63)] = g_te[(size_t)(pbase + (i>>6))*NA + (i&63)];
    int c4 = (tid & 63)*4, r0 = tid >> 6;
    for (int r = r0; r < 64; r += 4)
        *(float4*)&s_ws[r*260 + c4] = *(const float4*)&ws[(size_t)r*H + c4];
    __syncthreads();

    int ty = tid >> 5, tx = tid & 31;   // 8x32 grid -> 64 persons x 256 h
    float acc[8][8] = {};
    #pragma unroll 2
    for (int k = 0; k < 64; k++) {
        float4 w0 = *(float4*)&s_ws[k*260 + tx*8];
        float4 w1 = *(float4*)&s_ws[k*260 + tx*8 + 4];
        #pragma unroll
        for (int i = 0; i < 8; i++) {
            float t = s_te[(ty*8+i)*68 + k];
            acc[i][0] += t*w0.x; acc[i][1] += t*w0.y; acc[i][2] += t*w0.z; acc[i][3] += t*w0.w;
            acc[i][4] += t*w1.x; acc[i][5] += t*w1.y; acc[i][6] += t*w1.z; acc[i][7] += t*w1.w;
        }
    }
    int g = tx >> 3;     // (tx*8)/64
    #pragma unroll
    for (int i = 0; i < 8; i++) {
        int p = pbase + ty*8 + i;
        float4 o0, o1;
        o0.x = acc[i][0]; o0.y = acc[i][1]; o0.z = acc[i][2]; o0.w = acc[i][3];
        o1.x = acc[i][4]; o1.y = acc[i][5]; o1.z = acc[i][6]; o1.w = acc[i][7];
        *(float4*)&g_v[(size_t)p*H + tx*8]     = o0;
        *(float4*)&g_v[(size_t)p*H + tx*8 + 4] = o1;
        float part = o0.x+o0.y+o0.z+o0.w + o1.x+o1.y+o1.z+o1.w;
        atomicAdd(&g_Vg[p*4 + g], part);
    }
}

// ---------------- fused big pass 1: D[p,ch] dots + spat BN stats ----------------
// 1 warp per person, 8 lanes per 64-float channel row, coalesced 1KB per warp-iter
__global__ void __launch_bounds__(256) k_pass1(const float* __restrict__ xg) {
    __shared__ float s_sum[H], s_sq[H];
    int tid = threadIdx.x;
    s_sum[tid] = 0.f; s_sq[tid] = 0.f;
    __syncthreads();

    int warp = tid >> 5, lane = tid & 31;
    int p = blockIdx.x * 8 + warp;
    int rr = lane >> 3, seg = lane & 7;

    float vreg[8];
    const float* vp = &g_v[(size_t)p*H + rr*64 + seg*8];
    #pragma unroll
    for (int i = 0; i < 8; i++) vreg[i] = vp[i];

    const float* xp = xg + (size_t)p*(H*E) + lane*8;
    float* Dp = &g_D[(size_t)p*H];

    #pragma unroll 4
    for (int it = 0; it < 64; it++) {
        float4 a = *(const float4*)(xp + it*256);
        float4 b = *(const float4*)(xp + it*256 + 4);
        float dot = a.x*vreg[0] + a.y*vreg[1] + a.z*vreg[2] + a.w*vreg[3]
                  + b.x*vreg[4] + b.y*vreg[5] + b.z*vreg[6] + b.w*vreg[7];
        float s1 = a.x + a.y + a.z + a.w + b.x + b.y + b.z + b.w;
        float s2 = a.x*a.x + a.y*a.y + a.z*a.z + a.w*a.w
                 + b.x*b.x + b.y*b.y + b.z*b.z + b.w*b.w;
        #pragma unroll
        for (int o = 1; o < 8; o <<= 1) {
            dot += __shfl_xor_sync(0xffffffffu, dot, o);
            s1  += __shfl_xor_sync(0xffffffffu, s1,  o);
            s2  += __shfl_xor_sync(0xffffffffu, s2,  o);
        }
        if (seg == 0) {
            int ch = it*4 + rr;
            Dp[ch] = dot;
            atomicAdd(&s_sum[ch], s1);
            atomicAdd(&s_sq[ch],  s2);
        }
    }
    __syncthreads();
    atomicAdd(&g_ssum[tid],   s_sum[tid]);
    atomicAdd(&g_ssumsq[tid], s_sq[tid]);
}

// ---------------- finalize spat BN scale/shift ----------------
__global__ void k_sfin(const float* __restrict__ gamma, const float* __restrict__ beta) {
    int c = threadIdx.x;
    float inv = 1.0f / (float)PE;
    float m   = g_ssum[c] * inv;
    float var = g_ssumsq[c] * inv - m*m;
    float s   = gamma[c] * rsqrtf(var + 1e-5f);
    g_ss[c] = s;
    g_tt[c] = beta[c] - m*s;
}

// ---------------- attn scores (transposed store for softmax) ----------------
__global__ void __launch_bounds__(256) k_attn() {
    int p = blockIdx.x * 256 + threadIdx.x;
    float vg0 = g_Vg[p*4+0], vg1 = g_Vg[p*4+1], vg2 = g_Vg[p*4+2], vg3 = g_Vg[p*4+3];
    float cp = g_c[p];
    const float4* Dp  = (const float4*)&g_D[(size_t)p*H];
    const float4* ssp = (const float4*)g_ss;
    const float4* ttp = (const float4*)g_tt;
    const float T = 8.0f;   // E / sqrt(A) = 64/8
    #pragma unroll 8
    for (int e = 0; e < E; e++) {
        float4 d = Dp[e];
        float4 s = ssp[e];
        float4 t = ttp[e];
        float val = s.x*d.x + s.y*d.y + s.z*d.z + s.w*d.w
                  + t.x*vg0 + t.y*vg1 + t.z*vg2 + t.w*vg3 + cp;
        g_attnT[(size_t)e*P + p] = T * val;
    }
}

// ---------------- softmax over persons, per edge ----------------
__global__ void __launch_bounds__(1024) k_softmax() {
    __shared__ float red[32];
    __shared__ float bcast;
    int e = blockIdx.x, tid = threadIdx.x;
    const float* row = &g_attnT[(size_t)e*P];

    float mx = -1e30f;
    for (int i = tid; i < P; i += 1024) mx = fmaxf(mx, row[i]);
    #pragma unroll
    for (int o = 16; o; o >>= 1) mx = fmaxf(mx, __shfl_xor_sync(0xffffffffu, mx, o));
    if ((tid & 31) == 0) red[tid >> 5] = mx;
    __syncthreads();
    if (tid < 32) {
        float v = red[tid];
        #pragma unroll
        for (int o = 16; o; o >>= 1) v = fmaxf(v, __shfl_xor_sync(0xffffffffu, v, o));
        if (tid == 0) bcast = v;
    }
    __syncthreads();
    float m = bcast;
    __syncthreads();

    float s = 0.f;
    for (int i = tid; i < P; i += 1024) s += expf(row[i] - m);
    #pragma unroll
    for (int o = 16; o; o >>= 1) s += __shfl_xor_sync(0xffffffffu, s, o);
    if ((tid & 31) == 0) red[tid >> 5] = s;
    __syncthreads();
    if (tid < 32) {
        float v = red[tid];
        #pragma unroll
        for (int o = 16; o; o >>= 1) v += __shfl_xor_sync(0xffffffffu, v, o);
        if (tid == 0) bcast = v;
    }
    __syncthreads();
    float inv = 1.0f / bcast;

    for (int i = tid; i < P; i += 1024)
        g_wv[(size_t)i*E + e] = expf(row[i] - m) * inv;
}

// ---------------- final big pass 2: out[p,h] = sum_e wv*sr ----------------
// block per person, thread per output h; streams the whole 64KB person slab
__global__ void __launch_bounds__(256) k_out(const float* __restrict__ xg,
                                             float* __restrict__ out) {
    __shared__ float s_wv[E];
    __shared__ float coef[256];
    __shared__ float cg[4];
    int p = blockIdx.x, tid = threadIdx.x;
    if (tid < E) s_wv[tid] = g_wv[(size_t)p*E + tid];
    __syncthreads();
    {
        int e = tid >> 2, g = tid & 3;
        coef[tid] = s_wv[e] * g_ss[4*e + g];
    }
    if (tid < 4) {
        float s = 0.f;
        #pragma unroll
        for (int e = 0; e < E; e++) s += s_wv[e] * g_tt[4*e + tid];
        cg[tid] = s;
    }
    __syncthreads();

    int g = tid >> 6;
    const float* xp = xg + (size_t)p*(H*E) + tid;   // h == tid: offset e*256 + tid
    float a0 = 0.f, a1 = 0.f, a2 = 0.f, a3 = 0.f;
    #pragma unroll
    for (int e = 0; e < 64; e += 4) {
        a0 += coef[(e+0)*4 + g] * xp[(e+0)*256];
        a1 += coef[(e+1)*4 + g] * xp[(e+1)*256];
        a2 += coef[(e+2)*4 + g] * xp[(e+2)*256];
        a3 += coef[(e+3)*4 + g] * xp[(e+3)*256];
    }
    out[(size_t)p*H + tid] = a0 + a1 + a2 + a3 + cg[g];
}

// ---------------- launch ----------------
extern "C" void kernel_launch(void* const* d_in, const int* in_sizes, int n_in,
                              void* d_out, int out_size) {
    const float* th    = (const float*)d_in[0];
    const float* sh    = (const float*)d_in[1];
    const float* gamma = (const float*)d_in[2];
    const float* beta  = (const float*)d_in[3];
    const float* wt    = (const float*)d_in[4];
    const float* bt    = (const float*)d_in[5];
    const float* ws    = (const float*)d_in[6];
    const float* bs    = (const float*)d_in[7];
    float* out = (float*)d_out;

    size_t smem_te = (size_t)(64*260 + 256*68 + 512) * sizeof(float);   // ~138 KB
    size_t smem_v  = (size_t)(64*68 + 64*260) * sizeof(float);          // ~84 KB
    cudaFuncSetAttribute(k_te, cudaFuncAttributeMaxDynamicSharedMemorySize, (int)smem_te);
    cudaFuncSetAttribute(k_v,  cudaFuncAttributeMaxDynamicSharedMemorySize, (int)smem_v);

    k_init<<<256, 256>>>();
    k_tstats<<<128, 256>>>(th);
    k_te<<<P/64, 256, smem_te>>>(th, gamma, beta, wt, bt, bs);
    k_v<<<P/64, 256, smem_v>>>(ws);
    k_pass1<<<P/8, 256>>>(sh);
    k_sfin<<<1, 256>>>(gamma, beta);
    k_attn<<<P/256, 256>>>();
    k_softmax<<<E, 1024>>>();
    k_out<<<P, 256>>>(sh, out);
}

// round 5
// speedup vs baseline: 1.1172x; 1.1172x over previous
#include <cuda_runtime.h>

#define P 16384
#define H 256
#define E 64
#define NA 64
#define PE (P*E)

// ---------------- static scratch ----------------
__device__ float g_tsum[H], g_tsumsq[H];     // temp BN sums
__device__ float g_ssum[H], g_ssumsq[H];     // spat BN sums
__device__ float g_te[P*NA];                 // temporal embed [P,64]
__device__ float g_c[P];                     // c[p] = b_spat . te[p]
__device__ float g_v[P*H];                   // v[p,h]
__device__ float g_Vg[P*4];                  // group sums of v
__device__ float g_D[P*H];                   // raw dots
__device__ float g_ss[H], g_tt[H];           // spat BN scale/shift
__device__ float g_attnT[E*P];               // attn transposed; reused as wvT after softmax
__device__ float g_wv[P*E];                  // softmax weights [P][E]

// ---------------- init ----------------
__global__ void k_init() {
    int i = blockIdx.x * blockDim.x + threadIdx.x;
    int stride = gridDim.x * blockDim.x;
    if (i < H) { g_tsum[i] = 0.f; g_tsumsq[i] = 0.f; g_ssum[i] = 0.f; g_ssumsq[i] = 0.f; }
    for (int j = i; j < P; j += stride) g_c[j] = 0.f;
}

// ---------------- temp_hidden per-column stats ----------------
__global__ void k_tstats(const float* __restrict__ th) {
    int c = threadIdx.x;
    float s = 0.f, s2 = 0.f;
    for (int p = blockIdx.x; p < P; p += gridDim.x) {
        float x = th[(size_t)p*H + c];
        s += x; s2 += x*x;
    }
    atomicAdd(&g_tsum[c], s);
    atomicAdd(&g_tsumsq[c], s2);
}

// ---------------- te = BN(temp) @ w_temp^T + b_temp ; c[p] = te . b_spat ----------------
// 64 persons per block, K chunked 2x128 (smem ~71KB)
__global__ void __launch_bounds__(256) k_te(const float* __restrict__ th,
                                            const float* __restrict__ gamma,
                                            const float* __restrict__ beta,
                                            const float* __restrict__ wt,
                                            const float* __restrict__ bt,
                                            const float* __restrict__ bs) {
    extern __shared__ float sm[];
    float* s_a  = sm;                  // [64][132] normalized tn chunk
    float* s_w  = sm + 64*132;         // [128][68] transposed wt chunk (68: float4-aligned)
    float* s_sc = s_w + 128*68;        // [256]
    float* s_sh = s_sc + 256;          // [256]
    int tid = threadIdx.x;
    int pbase = blockIdx.x * 64;

    {
        float m   = g_tsum[tid]   * (1.0f/P);
        float var = g_tsumsq[tid] * (1.0f/P) - m*m;
        float s   = gamma[tid] * rsqrtf(var + 1e-5f);
        s_sc[tid] = s;
        s_sh[tid] = beta[tid] - m*s;
    }
    __syncthreads();

    int ty = tid >> 4, tx = tid & 15;       // 16x16 -> 64p x 64a (4x4 tile)
    float acc[4][4] = {};
    int c4 = (tid & 31) * 4, r0 = tid >> 5;

    for (int kc = 0; kc < 256; kc += 128) {
        // stage normalized A chunk [64 persons][128 k]
        for (int r = r0; r < 64; r += 8) {
            float4 x = *(const float4*)&th[(size_t)(pbase + r)*H + kc + c4];
            x.x = x.x*s_sc[kc+c4+0] + s_sh[kc+c4+0];
            x.y = x.y*s_sc[kc+c4+1] + s_sh[kc+c4+1];
            x.z = x.z*s_sc[kc+c4+2] + s_sh[kc+c4+2];
            x.w = x.w*s_sc[kc+c4+3] + s_sh[kc+c4+3];
            *(float4*)&s_a[r*132 + c4] = x;
        }
        // stage W chunk transposed [128 k][64 a]
        for (int r = r0; r < 64; r += 8) {
            float4 w = *(const float4*)&wt[(size_t)r*H + kc + c4];
            s_w[(c4+0)*68 + r] = w.x;
            s_w[(c4+1)*68 + r] = w.y;
            s_w[(c4+2)*68 + r] = w.z;
            s_w[(c4+3)*68 + r] = w.w;
        }
        __syncthreads();

        #pragma unroll 4
        for (int k = 0; k < 128; k++) {
            float a0 = s_a[(ty*4+0)*132 + k];
            float a1 = s_a[(ty*4+1)*132 + k];
            float a2 = s_a[(ty*4+2)*132 + k];
            float a3 = s_a[(ty*4+3)*132 + k];
            float4 b = *(float4*)&s_w[k*68 + tx*4];
            acc[0][0] += a0*b.x; acc[0][1] += a0*b.y; acc[0][2] += a0*b.z; acc[0][3] += a0*b.w;
            acc[1][0] += a1*b.x; acc[1][1] += a1*b.y; acc[1][2] += a1*b.z; acc[1][3] += a1*b.w;
            acc[2][0] += a2*b.x; acc[2][1] += a2*b.y; acc[2][2] += a2*b.z; acc[2][3] += a2*b.w;
            acc[3][0] += a3*b.x; acc[3][1] += a3*b.y; acc[3][2] += a3*b.z; acc[3][3] += a3*b.w;
        }
        __syncthreads();
    }

    float4 bt4 = *(const float4*)&bt[tx*4];
    float4 bs4 = *(const float4*)&bs[tx*4];
    #pragma unroll
    for (int i = 0; i < 4; i++) {
        int p = pbase + ty*4 + i;
        float4 t;
        t.x = acc[i][0] + bt4.x;
        t.y = acc[i][1] + bt4.y;
        t.z = acc[i][2] + bt4.z;
        t.w = acc[i][3] + bt4.w;
        *(float4*)&g_te[(size_t)p*NA + tx*4] = t;
        float cc = t.x*bs4.x + t.y*bs4.y + t.z*bs4.z + t.w*bs4.w;
        atomicAdd(&g_c[p], cc);
    }
}

// ---------------- v = te @ w_spat ; Vg group sums ----------------
// 32 persons x 256 h per block; thread = 4p x 8h (conflict-free smem)
__global__ void __launch_bounds__(256) k_v(const float* __restrict__ ws) {
    extern __shared__ float sm[];
    float* s_te = sm;                // [32][68]
    float* s_ws = sm + 32*68;        // [64][260]
    float* s_vg = s_ws + 64*260;     // [32][4]
    int tid = threadIdx.x, p0 = blockIdx.x * 32;

    if (tid < 128) s_vg[tid] = 0.f;
    for (int i = tid*4; i < 32*64; i += 1024) {
        int pr = i >> 6, c = i & 63;
        *(float4*)&s_te[pr*68 + c] = *(const float4*)&g_te[(size_t)(p0+pr)*NA + c];
    }
    for (int i = tid*4; i < 64*256; i += 1024) {
        int a = i >> 8, h = i & 255;
        *(float4*)&s_ws[a*260 + h] = *(const float4*)&ws[i];
    }
    __syncthreads();

    int ty = tid >> 5, tx = tid & 31;      // 8x32 -> 32p x 256h
    float acc[4][8] = {};
    #pragma unroll 4
    for (int a = 0; a < 64; a++) {
        float4 w0 = *(float4*)&s_ws[a*260 + tx*4];
        float4 w1 = *(float4*)&s_ws[a*260 + 128 + tx*4];
        #pragma unroll
        for (int i = 0; i < 4; i++) {
            float t = s_te[(ty*4+i)*68 + a];
            acc[i][0] += t*w0.x; acc[i][1] += t*w0.y; acc[i][2] += t*w0.z; acc[i][3] += t*w0.w;
            acc[i][4] += t*w1.x; acc[i][5] += t*w1.y; acc[i][6] += t*w1.z; acc[i][7] += t*w1.w;
        }
    }
    int g0 = tx >> 4;          // group of h = tx*4
    #pragma unroll
    for (int i = 0; i < 4; i++) {
        int pl = ty*4 + i;
        int p = p0 + pl;
        float4 o0, o1;
        o0.x = acc[i][0]; o0.y = acc[i][1]; o0.z = acc[i][2]; o0.w = acc[i][3];
        o1.x = acc[i][4]; o1.y = acc[i][5]; o1.z = acc[i][6]; o1.w = acc[i][7];
        *(float4*)&g_v[(size_t)p*H + tx*4]       = o0;
        *(float4*)&g_v[(size_t)p*H + 128 + tx*4] = o1;
        atomicAdd(&s_vg[pl*4 + g0],     o0.x+o0.y+o0.z+o0.w);
        atomicAdd(&s_vg[pl*4 + 2 + g0], o1.x+o1.y+o1.z+o1.w);
    }
    __syncthreads();
    if (tid < 128) g_Vg[(size_t)(p0 + (tid >> 2))*4 + (tid & 3)] = s_vg[tid];
}

// ---------------- fused big pass 1: D[p,ch] dots + spat BN stats ----------------
__global__ void __launch_bounds__(256) k_pass1(const float* __restrict__ xg) {
    __shared__ float s_sum[H], s_sq[H];
    __shared__ __align__(16) float s_D[8][256];
    int tid = threadIdx.x;
    s_sum[tid] = 0.f; s_sq[tid] = 0.f;
    __syncthreads();

    int warp = tid >> 5, lane = tid & 31;
    int p = blockIdx.x * 8 + warp;
    int rr = lane >> 3, seg = lane & 7;

    float vreg[8];
    const float* vp = &g_v[(size_t)p*H + rr*64 + seg*8];
    #pragma unroll
    for (int i = 0; i < 8; i++) vreg[i] = vp[i];

    const float* xp = xg + (size_t)p*(H*E) + lane*8;

    #pragma unroll 4
    for (int it = 0; it < 64; it++) {
        float4 a = *(const float4*)(xp + it*256);
        float4 b = *(const float4*)(xp + it*256 + 4);
        float dot = a.x*vreg[0] + a.y*vreg[1] + a.z*vreg[2] + a.w*vreg[3]
                  + b.x*vreg[4] + b.y*vreg[5] + b.z*vreg[6] + b.w*vreg[7];
        float s1 = a.x + a.y + a.z + a.w + b.x + b.y + b.z + b.w;
        float s2 = a.x*a.x + a.y*a.y + a.z*a.z + a.w*a.w
                 + b.x*b.x + b.y*b.y + b.z*b.z + b.w*b.w;
        #pragma unroll
        for (int o = 1; o < 8; o <<= 1) {
            dot += __shfl_xor_sync(0xffffffffu, dot, o);
            s1  += __shfl_xor_sync(0xffffffffu, s1,  o);
            s2  += __shfl_xor_sync(0xffffffffu, s2,  o);
        }
        if (seg == 0) {
            int ch = it*4 + rr;
            s_D[warp][ch] = dot;
            atomicAdd(&s_sum[ch], s1);
            atomicAdd(&s_sq[ch],  s2);
        }
    }
    __syncwarp();
    // coalesced D write
    float4 d0 = *(float4*)&s_D[warp][lane*4];
    float4 d1 = *(float4*)&s_D[warp][128 + lane*4];
    *(float4*)&g_D[(size_t)p*H + lane*4]       = d0;
    *(float4*)&g_D[(size_t)p*H + 128 + lane*4] = d1;

    __syncthreads();
    atomicAdd(&g_ssum[tid],   s_sum[tid]);
    atomicAdd(&g_ssumsq[tid], s_sq[tid]);
}

// ---------------- attn scores (sfin folded in; transposed store) ----------------
__global__ void __launch_bounds__(256) k_attn(const float* __restrict__ gamma,
                                              const float* __restrict__ beta) {
    __shared__ __align__(16) float ss[H];
    __shared__ __align__(16) float tt[H];
    int tid = threadIdx.x;
    {
        float inv = 1.0f / (float)PE;
        float m   = g_ssum[tid] * inv;
        float var = g_ssumsq[tid] * inv - m*m;
        float s   = gamma[tid] * rsqrtf(var + 1e-5f);
        ss[tid] = s;
        tt[tid] = beta[tid] - m*s;
        if (blockIdx.x == 0) { g_ss[tid] = s; g_tt[tid] = tt[tid]; }
    }
    __syncthreads();

    int p = blockIdx.x * 256 + tid;
    float vg0 = g_Vg[p*4+0], vg1 = g_Vg[p*4+1], vg2 = g_Vg[p*4+2], vg3 = g_Vg[p*4+3];
    float cp = g_c[p];
    const float4* Dp = (const float4*)&g_D[(size_t)p*H];
    const float T = 8.0f;   // E / sqrt(A)
    #pragma unroll 8
    for (int e = 0; e < E; e++) {
        float4 d = Dp[e];
        float4 s = *(float4*)&ss[e*4];
        float4 t = *(float4*)&tt[e*4];
        float val = s.x*d.x + s.y*d.y + s.z*d.z + s.w*d.w
                  + t.x*vg0 + t.y*vg1 + t.z*vg2 + t.w*vg3 + cp;
        g_attnT[(size_t)e*P + p] = T * val;
    }
}

// ---------------- softmax over persons (in-place, coalesced) ----------------
__global__ void __launch_bounds__(1024) k_softmax() {
    __shared__ float red[32];
    __shared__ float bcast;
    int e = blockIdx.x, tid = threadIdx.x;
    float* row = &g_attnT[(size_t)e*P];

    float mx = -1e30f;
    for (int i = tid; i < P; i += 1024) mx = fmaxf(mx, row[i]);
    #pragma unroll
    for (int o = 16; o; o >>= 1) mx = fmaxf(mx, __shfl_xor_sync(0xffffffffu, mx, o));
    if ((tid & 31) == 0) red[tid >> 5] = mx;
    __syncthreads();
    if (tid < 32) {
        float v = red[tid];
        #pragma unroll
        for (int o = 16; o; o >>= 1) v = fmaxf(v, __shfl_xor_sync(0xffffffffu, v, o));
        if (tid == 0) bcast = v;
    }
    __syncthreads();
    float m = bcast;
    __syncthreads();

    float s = 0.f;
    for (int i = tid; i < P; i += 1024) s += expf(row[i] - m);
    #pragma unroll
    for (int o = 16; o; o >>= 1) s += __shfl_xor_sync(0xffffffffu, s, o);
    if ((tid & 31) == 0) red[tid >> 5] = s;
    __syncthreads();
    if (tid < 32) {
        float v = red[tid];
        #pragma unroll
        for (int o = 16; o; o >>= 1) v += __shfl_xor_sync(0xffffffffu, v, o);
        if (tid == 0) bcast = v;
    }
    __syncthreads();
    float inv = 1.0f / bcast;

    for (int i = tid; i < P; i += 1024)
        row[i] = expf(row[i] - m) * inv;          // in-place: g_attnT now holds wv^T
}

// ---------------- transpose wv^T [E][P] -> wv [P][E] ----------------
__global__ void __launch_bounds__(256) k_tr() {
    __shared__ float s[64][65];
    int p0 = blockIdx.x * 64, tid = threadIdx.x;
    int er = tid >> 6, pc = tid & 63;
    #pragma unroll
    for (int ee = 0; ee < 64; ee += 4)
        s[ee + er][pc] = g_attnT[(size_t)(ee + er)*P + p0 + pc];
    __syncthreads();
    int pr = tid >> 6, ec = tid & 63;
    #pragma unroll
    for (int pp = 0; pp < 64; pp += 4)
        g_wv[(size_t)(p0 + pp + pr)*E + ec] = s[ec][pp + pr];
}

// ---------------- final big pass 2: out[p,h] = sum_e wv*sr ----------------
// block per person; 4-way e-split; float4 loads (MLP 16)
__global__ void __launch_bounds__(256) k_out(const float* __restrict__ xg,
                                             float* __restrict__ out) {
    __shared__ float s_wv[E];
    __shared__ float coef[256];
    __shared__ float cg[4];
    __shared__ __align__(16) float4 psum[256];
    int p = blockIdx.x, tid = threadIdx.x;
    if (tid < E) s_wv[tid] = g_wv[(size_t)p*E + tid];
    __syncthreads();
    coef[tid] = s_wv[tid >> 2] * g_ss[tid];        // ch = tid
    if (tid < 4) {
        float s = 0.f;
        #pragma unroll
        for (int e = 0; e < E; e++) s += s_wv[e] * g_tt[4*e + tid];
        cg[tid] = s;
    }
    __syncthreads();

    int q = tid >> 6, lane = tid & 63;
    int g = lane >> 4, ms = lane & 15;
    const float* xp = xg + (size_t)p*(H*E) + g*64 + ms*4;
    float4 acc = make_float4(0.f, 0.f, 0.f, 0.f);
    int e0 = q * 16;
    #pragma unroll
    for (int j = 0; j < 16; j++) {
        int e = e0 + j;
        float4 f = *(const float4*)(xp + e*256);
        float c = coef[4*e + g];
        acc.x += c*f.x; acc.y += c*f.y; acc.z += c*f.z; acc.w += c*f.w;
    }
    psum[tid] = acc;
    __syncthreads();

    if (tid < 64) {
        float4 a0 = psum[tid], a1 = psum[64 + tid], a2 = psum[128 + tid], a3 = psum[192 + tid];
        float b = cg[g];
        float4 t;
        t.x = a0.x + a1.x + a2.x + a3.x + b;
        t.y = a0.y + a1.y + a2.y + a3.y + b;
        t.z = a0.z + a1.z + a2.z + a3.z + b;
        t.w = a0.w + a1.w + a2.w + a3.w + b;
        *(float4*)&out[(size_t)p*H + g*64 + ms*4] = t;
    }
}

// ---------------- launch ----------------
extern "C" void kernel_launch(void* const* d_in, const int* in_sizes, int n_in,
                              void* d_out, int out_size) {
    const float* th    = (const float*)d_in[0];
    const float* sh    = (const float*)d_in[1];
    const float* gamma = (const float*)d_in[2];
    const float* beta  = (const float*)d_in[3];
    const float* wt    = (const float*)d_in[4];
    const float* bt    = (const float*)d_in[5];
    const float* ws    = (const float*)d_in[6];
    const float* bs    = (const float*)d_in[7];
    float* out = (float*)d_out;

    size_t smem_te = (size_t)(64*132 + 128*68 + 512) * sizeof(float);   // ~71 KB
    size_t smem_v  = (size_t)(32*68 + 64*260 + 128) * sizeof(float);    // ~76 KB
    cudaFuncSetAttribute(k_te, cudaFuncAttributeMaxDynamicSharedMemorySize, (int)smem_te);
    cudaFuncSetAttribute(k_v,  cudaFuncAttributeMaxDynamicSharedMemorySize, (int)smem_v);

    k_init<<<256, 256>>>();
    k_tstats<<<256, 256>>>(th);
    k_te<<<P/64, 256, smem_te>>>(th, gamma, beta, wt, bt, bs);
    k_v<<<P/32, 256, smem_v>>>(ws);
    k_pass1<<<P/8, 256>>>(sh);
    k_attn<<<P/256, 256>>>(gamma, beta);
    k_softmax<<<E, 1024>>>();
    k_tr<<<P/64, 256>>>();
    k_out<<<P, 256>>>(sh, out);
}

// round 9
// speedup vs baseline: 1.1203x; 1.0028x over previous
#include <cuda_runtime.h>

#define P 16384
#define H 256
#define E 64
#define NA 64
#define PE (P*E)

// ---------------- static scratch ----------------
__device__ float g_tsum[H], g_tsumsq[H];     // temp BN sums
__device__ float g_ssum[H], g_ssumsq[H];     // spat BN sums
__device__ float g_w2[NA*H];                 // BN-folded temporal weights [a][h]
__device__ float g_cA[NA];                   // folded bias for te
__device__ float g_c[P];                     // c[p] = b_spat . te[p]
__device__ float g_v[P*H];                   // v[p,h]
__device__ float g_Vg[P*4];                  // group sums of v
__device__ float g_D[P*H];                   // raw dots
__device__ float g_ss[H], g_tt[H];           // spat BN scale/shift
__device__ float g_attnT[E*P];               // attn transposed [E][P]
__device__ float g_wv[P*E];                  // softmax weights [P][E]
__device__ float g_pmax[E*4], g_psum[E*4];   // softmax partials (4 chunks per e)

// ---------------- init: zero accumulators ----------------
__global__ void k_init() {
    int i = threadIdx.x;
    g_tsum[i] = 0.f; g_tsumsq[i] = 0.f; g_ssum[i] = 0.f; g_ssumsq[i] = 0.f;
}

// ---------------- temp_hidden per-column stats ----------------
__global__ void k_tstats(const float* __restrict__ th) {
    int c = threadIdx.x;
    float s = 0.f, s2 = 0.f;
    for (int p = blockIdx.x; p < P; p += gridDim.x) {
        float x = th[(size_t)p*H + c];
        s += x; s2 += x*x;
    }
    atomicAdd(&g_tsum[c], s);
    atomicAdd(&g_tsumsq[c], s2);
}

// ---------------- prep: fold BN into temporal weights ----------------
// w2[a,h] = sc[h]*wt[a,h] ; cA[a] = bt[a] + sum_h sh[h]*wt[a,h]
__global__ void k_prep(const float* __restrict__ gamma,
                       const float* __restrict__ beta,
                       const float* __restrict__ wt,
                       const float* __restrict__ bt) {
    __shared__ float s_sh[H];
    int h = threadIdx.x;
    float m   = g_tsum[h]   * (1.0f/P);
    float var = g_tsumsq[h] * (1.0f/P) - m*m;
    float sc  = gamma[h] * rsqrtf(var + 1e-5f);
    float sh  = beta[h] - m*sc;
    s_sh[h] = sh;
    for (int a = 0; a < NA; a++)
        g_w2[a*H + h] = sc * wt[(size_t)a*H + h];
    __syncthreads();
    int w = h >> 5, lane = h & 31;
    for (int a = w; a < NA; a += 8) {
        float part = 0.f;
        for (int hh = lane; hh < H; hh += 32) part += s_sh[hh] * wt[(size_t)a*H + hh];
        #pragma unroll
        for (int o = 16; o; o >>= 1) part += __shfl_xor_sync(0xffffffffu, part, o);
        if (lane == 0) g_cA[a] = bt[a] + part;
    }
}

// ---------------- fused: te = th@w2^T + cA (smem) ; v = te@ws ; c, Vg ----------------
// 64 persons per block, 256 threads
__global__ void __launch_bounds__(256) k_tev(const float* __restrict__ th,
                                             const float* __restrict__ ws,
                                             const float* __restrict__ bs) {
    extern __shared__ float sm[];
    float* s_a  = sm;                  // [64][132] th chunk; later s_te [64][68]
    float* s_w  = sm + 64*132;         // [128][68] w2^T chunk; later s_ws [64][132]
    float* s_c  = s_w + 128*68;        // [64]
    float* s_vg = s_c + 64;            // [64][4]
    int tid = threadIdx.x;
    int pbase = blockIdx.x * 64;

    if (tid < 64)  s_c[tid] = 0.f;
    s_vg[tid] = 0.f;                   // 256 = 64*4 exactly
    __syncthreads();

    // ---- GEMM1: te[64p][64a] = th[64p][256h] @ w2^T ----
    int ty = tid >> 4, tx = tid & 15;          // 16x16 -> 4x4 tile
    int c4 = (tid & 31) * 4, r0 = tid >> 5;
    float acc[4][4] = {};

    for (int kc = 0; kc < 256; kc += 128) {
        for (int r = r0; r < 64; r += 8)
            *(float4*)&s_a[r*132 + c4] = *(const float4*)&th[(size_t)(pbase + r)*H + kc + c4];
        for (int r = r0; r < 64; r += 8) {
            float4 w = *(const float4*)&g_w2[r*H + kc + c4];
            s_w[(c4+0)*68 + r] = w.x;
            s_w[(c4+1)*68 + r] = w.y;
            s_w[(c4+2)*68 + r] = w.z;
            s_w[(c4+3)*68 + r] = w.w;
        }
        __syncthreads();
        #pragma unroll 4
        for (int k = 0; k < 128; k++) {
            float a0 = s_a[(ty*4+0)*132 + k];
            float a1 = s_a[(ty*4+1)*132 + k];
            float a2 = s_a[(ty*4+2)*132 + k];
            float a3 = s_a[(ty*4+3)*132 + k];
            float4 b = *(float4*)&s_w[k*68 + tx*4];
            acc[0][0] += a0*b.x; acc[0][1] += a0*b.y; acc[0][2] += a0*b.z; acc[0][3] += a0*b.w;
            acc[1][0] += a1*b.x; acc[1][1] += a1*b.y; acc[1][2] += a1*b.z; acc[1][3] += a1*b.w;
            acc[2][0] += a2*b.x; acc[2][1] += a2*b.y; acc[2][2] += a2*b.z; acc[2][3] += a2*b.w;
            acc[3][0] += a3*b.x; acc[3][1] += a3*b.y; acc[3][2] += a3*b.z; acc[3][3] += a3*b.w;
        }
        __syncthreads();
    }

    // te epilogue: add cA, write into s_te (reuse s_a), accumulate c[p]
    float* s_te = s_a;                 // [64][68]
    {
        float4 cA4 = *(const float4*)&g_cA[tx*4];
        float4 bs4 = *(const float4*)&bs[tx*4];
        #pragma unroll
        for (int i = 0; i < 4; i++) {
            int pl = ty*4 + i;
            float t0 = acc[i][0] + cA4.x;
            float t1 = acc[i][1] + cA4.y;
            float t2 = acc[i][2] + cA4.z;
            float t3 = acc[i][3] + cA4.w;
            s_te[pl*68 + tx*4 + 0] = t0;
            s_te[pl*68 + tx*4 + 1] = t1;
            s_te[pl*68 + tx*4 + 2] = t2;
            s_te[pl*68 + tx*4 + 3] = t3;
            atomicAdd(&s_c[pl], t0*bs4.x + t1*bs4.y + t2*bs4.z + t3*bs4.w);
        }
    }
    __syncthreads();

    // ---- GEMM2: v[64p][256h] = te[64p][64a] @ ws[64a][256h] ----
    float* s_ws = s_w;                 // [64][132]
    int ty2 = tid >> 5, tx2 = tid & 31;     // 8x32 -> 8p x 4h tile per chunk
    for (int hc = 0; hc < 256; hc += 128) {
        for (int r = r0; r < 64; r += 8)
            *(float4*)&s_ws[r*132 + c4] = *(const float4*)&ws[(size_t)r*H + hc + c4];
        __syncthreads();
        float a2c[8][4] = {};
        #pragma unroll 4
        for (int a = 0; a < 64; a++) {
            float4 w = *(float4*)&s_ws[a*132 + tx2*4];
            #pragma unroll
            for (int i = 0; i < 8; i++) {
                float t = s_te[(ty2*8+i)*68 + a];
                a2c[i][0] += t*w.x; a2c[i][1] += t*w.y; a2c[i][2] += t*w.z; a2c[i][3] += t*w.w;
            }
        }
        int g = (hc >> 6) + (tx2 >> 4);
        #pragma unroll
        for (int i = 0; i < 8; i++) {
            int pl = ty2*8 + i;
            float4 o;
            o.x = a2c[i][0]; o.y = a2c[i][1]; o.z = a2c[i][2]; o.w = a2c[i][3];
            *(float4*)&g_v[(size_t)(pbase + pl)*H + hc + tx2*4] = o;
            atomicAdd(&s_vg[pl*4 + g], o.x + o.y + o.z + o.w);
        }
        __syncthreads();
    }

    g_Vg[(size_t)pbase*4 + tid] = s_vg[tid];
    if (tid < 64) g_c[pbase + tid] = s_c[tid];
}

// ---------------- fused big pass 1: D[p,ch] dots + spat BN stats ----------------
__global__ void __launch_bounds__(256) k_pass1(const float* __restrict__ xg) {
    __shared__ float s_sum[H], s_sq[H];
    __shared__ __align__(16) float s_D[8][256];
    int tid = threadIdx.x;
    s_sum[tid] = 0.f; s_sq[tid] = 0.f;
    __syncthreads();

    int warp = tid >> 5, lane = tid & 31;
    int p = blockIdx.x * 8 + warp;
    int rr = lane >> 3, seg = lane & 7;

    float vreg[8];
    const float* vp = &g_v[(size_t)p*H + lane*8];
    #pragma unroll
    for (int i = 0; i < 8; i++) vreg[i] = vp[i];

    const float* xp = xg + (size_t)p*(H*E) + lane*8;

    #pragma unroll 4
    for (int it = 0; it < 64; it++) {
        float4 a = *(const float4*)(xp + it*256);
        float4 b = *(const float4*)(xp + it*256 + 4);
        float dot = a.x*vreg[0] + a.y*vreg[1] + a.z*vreg[2] + a.w*vreg[3]
                  + b.x*vreg[4] + b.y*vreg[5] + b.z*vreg[6] + b.w*vreg[7];
        float s1 = a.x + a.y + a.z + a.w + b.x + b.y + b.z + b.w;
        float s2 = a.x*a.x + a.y*a.y + a.z*a.z + a.w*a.w
                 + b.x*b.x + b.y*b.y + b.z*b.z + b.w*b.w;
        #pragma unroll
        for (int o = 1; o < 8; o <<= 1) {
            dot += __shfl_xor_sync(0xffffffffu, dot, o);
            s1  += __shfl_xor_sync(0xffffffffu, s1,  o);
            s2  += __shfl_xor_sync(0xffffffffu, s2,  o);
        }
        if (seg == 0) {
            int ch = it*4 + rr;
            s_D[warp][ch] = dot;
            atomicAdd(&s_sum[ch], s1);
            atomicAdd(&s_sq[ch],  s2);
        }
    }
    __syncwarp();
    float4 d0 = *(float4*)&s_D[warp][lane*4];
    float4 d1 = *(float4*)&s_D[warp][128 + lane*4];
    *(float4*)&g_D[(size_t)p*H + lane*4]       = d0;
    *(float4*)&g_D[(size_t)p*H + 128 + lane*4] = d1;

    __syncthreads();
    atomicAdd(&g_ssum[tid],   s_sum[tid]);
    atomicAdd(&g_ssumsq[tid], s_sq[tid]);
}

// ---------------- attn scores (BN finalize folded in; 4-way e-split) ----------------
__global__ void __launch_bounds__(256) k_attn(const float* __restrict__ gamma,
                                              const float* __restrict__ beta) {
    __shared__ __align__(16) float ss[H];
    __shared__ __align__(16) float tt[H];
    int tid = threadIdx.x;
    {
        float inv = 1.0f / (float)PE;
        float m   = g_ssum[tid] * inv;
        float var = g_ssumsq[tid] * inv - m*m;
        float s   = gamma[tid] * rsqrtf(var + 1e-5f);
        ss[tid] = s;
        tt[tid] = beta[tid] - m*s;
        if (blockIdx.x == 0) { g_ss[tid] = s; g_tt[tid] = tt[tid]; }
    }
    __syncthreads();

    int pb = blockIdx.x & 63, ec = blockIdx.x >> 6;
    int p = pb*256 + tid;
    float vg0 = g_Vg[p*4+0], vg1 = g_Vg[p*4+1], vg2 = g_Vg[p*4+2], vg3 = g_Vg[p*4+3];
    float cp = g_c[p];
    const float4* Dp = (const float4*)&g_D[(size_t)p*H];
    const float T = 8.0f;   // E / sqrt(A)
    #pragma unroll
    for (int e = ec*16; e < ec*16 + 16; e++) {
        float4 d = Dp[e];
        float4 s = *(float4*)&ss[e*4];
        float4 t = *(float4*)&tt[e*4];
        float val = s.x*d.x + s.y*d.y + s.z*d.z + s.w*d.w
                  + t.x*vg0 + t.y*vg1 + t.z*vg2 + t.w*vg3 + cp;
        g_attnT[(size_t)e*P + p] = T * val;
    }
}

// ---------------- softmax stage 1: per-(e,chunk) max + sumexp ----------------
__global__ void __launch_bounds__(256) k_sm1() {
    __shared__ float red[32];
    __shared__ float bmax;
    int tid = threadIdx.x;
    const float* row = &g_attnT[(size_t)(blockIdx.x >> 2)*P + (blockIdx.x & 3)*4096];

    float mx = -1e30f;
    for (int i = tid; i < 4096; i += 256) mx = fmaxf(mx, row[i]);
    #pragma unroll
    for (int o = 16; o; o >>= 1) mx = fmaxf(mx, __shfl_xor_sync(0xffffffffu, mx, o));
    if ((tid & 31) == 0) red[tid >> 5] = mx;
    __syncthreads();
    if (tid < 32) {
        float v = (tid < 8) ? red[tid] : -1e30f;
        #pragma unroll
        for (int o = 4; o; o >>= 1) v = fmaxf(v, __shfl_xor_sync(0xffffffffu, v, o));
        if (tid == 0) bmax = v;
    }
    __syncthreads();
    float m = bmax;

    float s = 0.f;
    for (int i = tid; i < 4096; i += 256) s += expf(row[i] - m);
    #pragma unroll
    for (int o = 16; o; o >>= 1) s += __shfl_xor_sync(0xffffffffu, s, o);
    if ((tid & 31) == 0) red[tid >> 5] = s;
    __syncthreads();
    if (tid < 32) {
        float v = (tid < 8) ? red[tid] : 0.f;
        #pragma unroll
        for (int o = 4; o; o >>= 1) v += __shfl_xor_sync(0xffffffffu, v, o);
        if (tid == 0) { g_pmax[blockIdx.x] = m; g_psum[blockIdx.x] = v; }
    }
}

// ---------------- normalize + transpose: wv[p][e] = exp(attnT-M)*invS ----------------
__global__ void __launch_bounds__(256) k_trn() {
    __shared__ float sM[64], sInv[64];
    __shared__ float stile[64][65];
    int p0 = blockIdx.x * 64, tid = threadIdx.x;
    if (tid < 64) {
        float m0 = g_pmax[tid*4+0], m1 = g_pmax[tid*4+1];
        float m2 = g_pmax[tid*4+2], m3 = g_pmax[tid*4+3];
        float M = fmaxf(fmaxf(m0, m1), fmaxf(m2, m3));
        float S = g_psum[tid*4+0]*expf(m0-M) + g_psum[tid*4+1]*expf(m1-M)
                + g_psum[tid*4+2]*expf(m2-M) + g_psum[tid*4+3]*expf(m3-M);
        sM[tid] = M; sInv[tid] = 1.0f / S;
    }
    __syncthreads();
    int er = tid >> 6, pc = tid & 63;
    #pragma unroll
    for (int ee = 0; ee < 64; ee += 4) {
        float a = g_attnT[(size_t)(ee + er)*P + p0 + pc];
        stile[ee + er][pc] = expf(a - sM[ee + er]) * sInv[ee + er];
    }
    __syncthreads();
    int pr = tid >> 6, ec = tid & 63;
    #pragma unroll
    for (int pp = 0; pp < 64; pp += 4)
        g_wv[(size_t)(p0 + pp + pr)*E + ec] = stile[ec][pp + pr];
}

// ---------------- final big pass 2: warp-per-person streaming ----------------
__global__ void __launch_bounds__(256) k_out(const float* __restrict__ xg,
                                             float* __restrict__ out) {
    __shared__ float s_ss[H], s_tt[H];
    __shared__ float scoef[8][260];
    __shared__ float scg[8][4];
    int tid = threadIdx.x, warp = tid >> 5, lane = tid & 31;
    s_ss[tid] = g_ss[tid];
    s_tt[tid] = g_tt[tid];
    __syncthreads();

    int p = blockIdx.x * 8 + warp;
    float wv0 = g_wv[(size_t)p*E + lane];
    float wv1 = g_wv[(size_t)p*E + 32 + lane];
    float cgp0 = 0.f, cgp1 = 0.f, cgp2 = 0.f, cgp3 = 0.f;
    #pragma unroll
    for (int g = 0; g < 4; g++) {
        scoef[warp][4*lane + g]      = wv0 * s_ss[4*lane + g];
        scoef[warp][4*(lane+32) + g] = wv1 * s_ss[4*(lane+32) + g];
    }
    cgp0 = wv0*s_tt[4*lane+0] + wv1*s_tt[4*(lane+32)+0];
    cgp1 = wv0*s_tt[4*lane+1] + wv1*s_tt[4*(lane+32)+1];
    cgp2 = wv0*s_tt[4*lane+2] + wv1*s_tt[4*(lane+32)+2];
    cgp3 = wv0*s_tt[4*lane+3] + wv1*s_tt[4*(lane+32)+3];
    #pragma unroll
    for (int o = 16; o; o >>= 1) {
        cgp0 += __shfl_xor_sync(0xffffffffu, cgp0, o);
        cgp1 += __shfl_xor_sync(0xffffffffu, cgp1, o);
        cgp2 += __shfl_xor_sync(0xffffffffu, cgp2, o);
        cgp3 += __shfl_xor_sync(0xffffffffu, cgp3, o);
    }
    if (lane == 0) {
        scg[warp][0] = cgp0; scg[warp][1] = cgp1;
        scg[warp][2] = cgp2; scg[warp][3] = cgp3;
    }
    __syncwarp();

    int rr = lane >> 3;
    const float* xp = xg + (size_t)p*(H*E) + lane*8;
    float a0=0.f,a1=0.f,a2=0.f,a3=0.f,a4=0.f,a5=0.f,a6=0.f,a7=0.f;
    #pragma unroll 4
    for (int e = 0; e < 64; e++) {
        float4 f0 = *(const float4*)(xp + e*256);
        float4 f1 = *(const float4*)(xp + e*256 + 4);
        float cc = scoef[warp][4*e + rr];
        a0 += cc*f0.x; a1 += cc*f0.y; a2 += cc*f0.z; a3 += cc*f0.w;
        a4 += cc*f1.x; a5 += cc*f1.y; a6 += cc*f1.z; a7 += cc*f1.w;
    }
    float b = scg[warp][rr];
    float4 o0, o1;
    o0.x = a0+b; o0.y = a1+b; o0.z = a2+b; o0.w = a3+b;
    o1.x = a4+b; o1.y = a5+b; o1.z = a6+b; o1.w = a7+b;
    *(float4*)&out[(size_t)p*H + lane*8]     = o0;
    *(float4*)&out[(size_t)p*H + lane*8 + 4] = o1;
}

// ---------------- launch ----------------
extern "C" void kernel_launch(void* const* d_in, const int* in_sizes, int n_in,
                              void* d_out, int out_size) {
    const float* th    = (const float*)d_in[0];
    const float* sh    = (const float*)d_in[1];
    const float* gamma = (const float*)d_in[2];
    const float* beta  = (const float*)d_in[3];
    const float* wt    = (const float*)d_in[4];
    const float* bt    = (const float*)d_in[5];
    const float* ws    = (const float*)d_in[6];
    const float* bs    = (const float*)d_in[7];
    float* out = (float*)d_out;

    size_t smem_tev = (size_t)(64*132 + 128*68 + 64 + 256) * sizeof(float);  // ~70 KB
    cudaFuncSetAttribute(k_tev, cudaFuncAttributeMaxDynamicSharedMemorySize, (int)smem_tev);

    k_init<<<1, 256>>>();
    k_tstats<<<256, 256>>>(th);
    k_prep<<<1, 256>>>(gamma, beta, wt, bt);
    k_tev<<<P/64, 256, smem_tev>>>(th, ws, bs);
    k_pass1<<<P/8, 256>>>(sh);
    k_attn<<<256, 256>>>(gamma, beta);
    k_sm1<<<E*4, 256>>>();
    k_trn<<<P/64, 256>>>();
    k_out<<<P/8, 256>>>(sh, out);
}